// round 6
// baseline (speedup 1.0000x reference)
#include <cuda_runtime.h>

// Problem constants
#define NN 50000   // nodes
#define KK 10      // sampled neighbors per node
#define FF 128     // embedding dim
#define HH 64      // hidden per direction
#define GG 256     // 4*H gate width
#define BF 4       // nodes per CTA
#define RR (BF*KK) // 40 gathered rows per CTA

typedef unsigned long long u64;

// ---------------- packed f32x2 helpers (sm_103a FFMA2 path) ----------------
__device__ __forceinline__ void fma2(u64& d, u64 a, u64 b) {
    asm("fma.rn.f32x2 %0, %1, %2, %0;" : "+l"(d) : "l"(a), "l"(b));
}
__device__ __forceinline__ void unpack2(u64 v, float& lo, float& hi) {
    unsigned a, b;
    asm("mov.b64 {%0, %1}, %2;" : "=r"(a), "=r"(b) : "l"(v));
    lo = __uint_as_float(a); hi = __uint_as_float(b);
}

// ---------------- transcendentals (fast, ~1e-6; tolerance is 1e-3) ---------
__device__ __forceinline__ float sigf(float x) {
    return __fdividef(1.0f, 1.0f + __expf(-x));
}
__device__ __forceinline__ float tanh_fast(float x) {
    x = fminf(fmaxf(x, -9.0f), 9.0f);
    float e = __expf(-2.0f * x);
    return __fdividef(1.0f - e, 1.0f + e);
}

// ============================================================================
// Fully fused kernel, 2 CTAs/SM (16 warps). CTA = 4 nodes, 256 threads.
// Thread owns gate column c = tid for all 4 nodes; weight rows Wih[c], Whh[c],
// Wihb[c] live in REGISTERS (direct LDG, L1/L2-cached), never in smem.
//
// Shared memory (floats):
//   x_s   [40][128]   5120   gathered embeddings (warp-broadcast reads)
//   xg    [40][256]  10240   input projections + biases
//   gates [4][256]    1024   per-step gate staging (col->cell transpose)
//   h_s   [4][64]      256   hidden state
//   total 16640 floats = 66560 bytes  -> 2 CTAs/SM
// ============================================================================
#define SM_FLOATS 16640

__global__ __launch_bounds__(256, 2)
void lstm_kernel(const int*   __restrict__ nidx,
                 const float* __restrict__ embed,
                 const float* __restrict__ Wih,
                 const float* __restrict__ Whh,
                 const float* __restrict__ bih,
                 const float* __restrict__ bhh,
                 const float* __restrict__ Wihb,
                 const float* __restrict__ bihb,
                 const float* __restrict__ bhhb,
                 float*       __restrict__ out)
{
    extern __shared__ float sm[];
    float* x_s   = sm;             //  5120
    float* xg    = sm + 5120;      // 10240
    float* gates = sm + 15360;     //  1024
    float* h_s   = sm + 16384;     //   256

    const int tid  = threadIdx.x;
    const int lane = tid & 31;
    const int wrp  = tid >> 5;
    const int n0   = blockIdx.x * BF;

    // ---- gather embeddings: warp w loads rows w, w+8, ..., w+32 ----
    #pragma unroll
    for (int i = 0; i < 5; ++i) {
        int row  = wrp + i * 8;
        int node = row / KK, k = row % KK;
        int idx  = nidx[(n0 + node) * KK + k];      // uniform across warp
        float4 v = reinterpret_cast<const float4*>(embed)[idx * (FF / 4) + lane];
        reinterpret_cast<float4*>(x_s + row * FF)[lane] = v;
    }
    __syncthreads();

    // =========== forward input-projection GEMM ===========
    // acc2[r] = packed (sum over even f, sum over odd f) for col c=tid, row r.
    u64 acc2[RR];
    #pragma unroll
    for (int r = 0; r < RR; ++r) acc2[r] = 0ull;

    {
        const float* wrow = Wih + tid * FF;         // this thread's weight row
        #pragma unroll 1
        for (int cc = 0; cc < 8; ++cc) {            // 16 f's per chunk
            const int f0 = cc * 16;
            u64 w2[8];
            #pragma unroll
            for (int q = 0; q < 4; ++q) {
                ulonglong2 t = reinterpret_cast<const ulonglong2*>(wrow + f0)[q];
                w2[2 * q] = t.x; w2[2 * q + 1] = t.y;
            }
            #pragma unroll
            for (int r = 0; r < RR; ++r) {
                const ulonglong2* xp =
                    reinterpret_cast<const ulonglong2*>(x_s + r * FF + f0);
                ulonglong2 a0 = xp[0], a1 = xp[1], a2 = xp[2], a3 = xp[3];
                fma2(acc2[r], a0.x, w2[0]); fma2(acc2[r], a0.y, w2[1]);
                fma2(acc2[r], a1.x, w2[2]); fma2(acc2[r], a1.y, w2[3]);
                fma2(acc2[r], a2.x, w2[4]); fma2(acc2[r], a2.y, w2[5]);
                fma2(acc2[r], a3.x, w2[6]); fma2(acc2[r], a3.y, w2[7]);
            }
        }
        // epilogue: reduce pair-sums, add bias, park in xg (writer == reader)
        float bsum = bih[tid] + bhh[tid];
        #pragma unroll
        for (int r = 0; r < RR; ++r) {
            float lo, hi; unpack2(acc2[r], lo, hi);
            xg[r * GG + tid] = lo + hi + bsum;
        }
    }

    // =========== fused backward single step ===========
    // Backward stream runs exactly one step from h0=c0=0, so Whh_b and the
    // forget gate vanish: h_b = sig(o) * tanh( sig(i) * tanh(g) ) from
    // gates = x[:,K-1] @ Wihb^T + bihb + bhhb.  Skip f-gate columns.
    if ((tid >> 6) != 1) {
        u64 ab2[BF] = {0ull, 0ull, 0ull, 0ull};
        const float* wbrow = Wihb + tid * FF;
        #pragma unroll 1
        for (int cc = 0; cc < 8; ++cc) {
            const int f0 = cc * 16;
            u64 w2[8];
            #pragma unroll
            for (int q = 0; q < 4; ++q) {
                ulonglong2 t = reinterpret_cast<const ulonglong2*>(wbrow + f0)[q];
                w2[2 * q] = t.x; w2[2 * q + 1] = t.y;
            }
            #pragma unroll
            for (int b = 0; b < BF; ++b) {
                const ulonglong2* xp = reinterpret_cast<const ulonglong2*>(
                    x_s + (b * KK + (KK - 1)) * FF + f0);
                ulonglong2 a0 = xp[0], a1 = xp[1], a2 = xp[2], a3 = xp[3];
                fma2(ab2[b], a0.x, w2[0]); fma2(ab2[b], a0.y, w2[1]);
                fma2(ab2[b], a1.x, w2[2]); fma2(ab2[b], a1.y, w2[3]);
                fma2(ab2[b], a2.x, w2[4]); fma2(ab2[b], a2.y, w2[5]);
                fma2(ab2[b], a3.x, w2[6]); fma2(ab2[b], a3.y, w2[7]);
            }
        }
        float bsb = bihb[tid] + bhhb[tid];
        #pragma unroll
        for (int b = 0; b < BF; ++b) {
            float lo, hi; unpack2(ab2[b], lo, hi);
            gates[b * GG + tid] = lo + hi + bsb;
        }
    }
    __syncthreads();

    // backward activation: thread owns (node cb, cell cj); write out[:,64:128]
    const int cb = tid >> 6, cj = tid & 63;
    {
        float gi = gates[cb * GG +       cj];
        float gg = gates[cb * GG + 128 + cj];
        float go = gates[cb * GG + 192 + cj];
        float cv = sigf(gi) * tanh_fast(gg);
        out[(n0 + cb) * (2 * HH) + HH + cj] = sigf(go) * tanh_fast(cv);
    }

    // ---- register-cache this thread's Whh row as 32 packed pairs ----
    u64 wpair[32];
    {
        const ulonglong2* hrow =
            reinterpret_cast<const ulonglong2*>(Whh + tid * HH);
        #pragma unroll
        for (int q = 0; q < 16; ++q) {
            ulonglong2 t = hrow[q];
            wpair[2 * q] = t.x; wpair[2 * q + 1] = t.y;
        }
    }
    __syncthreads();   // backward reads of gates done -> reuse for recurrence

    // =========== forward recurrence: 10 steps ===========
    float cst = 0.0f, hout = 0.0f;

    #pragma unroll 1
    for (int k = 0; k < KK; ++k) {
        // col phase: thread computes gate col c=tid for all 4 nodes
        float gv[BF];
        #pragma unroll
        for (int b = 0; b < BF; ++b) {
            float g = xg[(b * KK + k) * GG + tid];
            if (k > 0) {
                u64 s2 = 0ull;
                const ulonglong2* h2 =
                    reinterpret_cast<const ulonglong2*>(h_s + b * HH);
                #pragma unroll
                for (int q = 0; q < 16; ++q) {
                    ulonglong2 hv = h2[q];          // warp-broadcast
                    fma2(s2, hv.x, wpair[2 * q]);
                    fma2(s2, hv.y, wpair[2 * q + 1]);
                }
                float lo, hi; unpack2(s2, lo, hi);
                g += lo + hi;
            }
            gv[b] = g;
        }
        #pragma unroll
        for (int b = 0; b < BF; ++b) gates[b * GG + tid] = gv[b];
        __syncthreads();

        // cell phase: thread owns cell (cb, cj)
        {
            float gi = gates[cb * GG +       cj];
            float gf = gates[cb * GG +  64 + cj];
            float gg = gates[cb * GG + 128 + cj];
            float go = gates[cb * GG + 192 + cj];
            float iv = sigf(gi), fv = sigf(gf);
            float gvv = tanh_fast(gg), ov = sigf(go);
            cst  = (k == 0) ? iv * gvv : fmaf(fv, cst, iv * gvv);
            hout = ov * tanh_fast(cst);
            h_s[cb * HH + cj] = hout;
        }
        __syncthreads();
    }

    // ---- write h_f into out[:, 0:64] ----
    out[(n0 + cb) * (2 * HH) + cj] = hout;
}

// ============================================================================
// Launch
// ============================================================================
extern "C" void kernel_launch(void* const* d_in, const int* in_sizes, int n_in,
                              void* d_out, int out_size)
{
    const int*   nidx  = (const int*)  d_in[0];
    const float* embed = (const float*)d_in[1];
    const float* Wih_f = (const float*)d_in[2];
    const float* Whh_f = (const float*)d_in[3];
    const float* bih_f = (const float*)d_in[4];
    const float* bhh_f = (const float*)d_in[5];
    const float* Wih_b = (const float*)d_in[6];
    // d_in[7] = Whh_b: provably unused (single backward step from h0 = 0)
    const float* bih_b = (const float*)d_in[8];
    const float* bhh_b = (const float*)d_in[9];
    float* out = (float*)d_out;

    const size_t smem = SM_FLOATS * sizeof(float);  // 66560 B
    cudaFuncSetAttribute(lstm_kernel,
                         cudaFuncAttributeMaxDynamicSharedMemorySize, (int)smem);

    lstm_kernel<<<NN / BF, 256, smem>>>(nidx, embed,
                                        Wih_f, Whh_f, bih_f, bhh_f,
                                        Wih_b, bih_b, bhh_b, out);
}

// round 7
// speedup vs baseline: 1.0003x; 1.0003x over previous
#include <cuda_runtime.h>

// Problem constants
#define NN 50000   // nodes
#define KK 10      // sampled neighbors per node
#define FF 128     // embedding dim
#define HH 64      // hidden per direction
#define GG 256     // 4*H gate width
#define BF 4       // nodes per CTA
#define RR (BF*KK) // 40 gathered rows per CTA

typedef unsigned long long u64;

// ---------------- packed f32x2 helpers (sm_103a FFMA2 path) ----------------
__device__ __forceinline__ void fma2(u64& d, u64 a, u64 b) {
    asm("fma.rn.f32x2 %0, %1, %2, %0;" : "+l"(d) : "l"(a), "l"(b));
}
__device__ __forceinline__ void unpack2(u64 v, float& lo, float& hi) {
    unsigned a, b;
    asm("mov.b64 {%0, %1}, %2;" : "=r"(a), "=r"(b) : "l"(v));
    lo = __uint_as_float(a); hi = __uint_as_float(b);
}

// ---------------- transcendentals (fast, ~1e-6; tolerance is 1e-3) ---------
__device__ __forceinline__ float sigf(float x) {
    return __fdividef(1.0f, 1.0f + __expf(-x));
}
__device__ __forceinline__ float tanh_fast(float x) {
    x = fminf(fmaxf(x, -9.0f), 9.0f);
    float e = __expf(-2.0f * x);
    return __fdividef(1.0f - e, 1.0f + e);
}

// ============================================================================
// Fully fused kernel, 2 CTAs/SM (16 warps). CTA = 4 nodes, 256 threads.
// Thread owns gate column c = tid for all 4 nodes; weight rows Wih[c], Whh[c],
// Wihb[c] live in REGISTERS (direct LDG, L1/L2-cached), never in smem.
//
// Shared memory (floats):
//   x_s   [40][128]   5120   gathered embeddings (warp-broadcast reads)
//   xg    [40][256]  10240   input projections + biases
//   gates [4][256]    1024   per-step gate staging (col->cell transpose)
//   h_s   [4][64]      256   hidden state
//   total 16640 floats = 66560 bytes  -> 2 CTAs/SM
// ============================================================================
#define SM_FLOATS 16640

__global__ __launch_bounds__(256, 2)
void lstm_kernel(const int*   __restrict__ nidx,
                 const float* __restrict__ embed,
                 const float* __restrict__ Wih,
                 const float* __restrict__ Whh,
                 const float* __restrict__ bih,
                 const float* __restrict__ bhh,
                 const float* __restrict__ Wihb,
                 const float* __restrict__ bihb,
                 const float* __restrict__ bhhb,
                 float*       __restrict__ out)
{
    extern __shared__ float sm[];
    float* x_s   = sm;             //  5120
    float* xg    = sm + 5120;      // 10240
    float* gates = sm + 15360;     //  1024
    float* h_s   = sm + 16384;     //   256

    const int tid  = threadIdx.x;
    const int lane = tid & 31;
    const int wrp  = tid >> 5;
    const int n0   = blockIdx.x * BF;

    // ---- gather embeddings: warp w loads rows w, w+8, ..., w+32 ----
    #pragma unroll
    for (int i = 0; i < 5; ++i) {
        int row  = wrp + i * 8;
        int node = row / KK, k = row % KK;
        int idx  = nidx[(n0 + node) * KK + k];      // uniform across warp
        float4 v = reinterpret_cast<const float4*>(embed)[idx * (FF / 4) + lane];
        reinterpret_cast<float4*>(x_s + row * FF)[lane] = v;
    }
    __syncthreads();

    // =========== forward input-projection GEMM ===========
    // acc2[r] = packed (sum over even f, sum over odd f) for col c=tid, row r.
    u64 acc2[RR];
    #pragma unroll
    for (int r = 0; r < RR; ++r) acc2[r] = 0ull;

    {
        const float* wrow = Wih + tid * FF;         // this thread's weight row
        #pragma unroll 1
        for (int cc = 0; cc < 8; ++cc) {            // 16 f's per chunk
            const int f0 = cc * 16;
            u64 w2[8];
            #pragma unroll
            for (int q = 0; q < 4; ++q) {
                ulonglong2 t = reinterpret_cast<const ulonglong2*>(wrow + f0)[q];
                w2[2 * q] = t.x; w2[2 * q + 1] = t.y;
            }
            #pragma unroll
            for (int r = 0; r < RR; ++r) {
                const ulonglong2* xp =
                    reinterpret_cast<const ulonglong2*>(x_s + r * FF + f0);
                ulonglong2 a0 = xp[0], a1 = xp[1], a2 = xp[2], a3 = xp[3];
                fma2(acc2[r], a0.x, w2[0]); fma2(acc2[r], a0.y, w2[1]);
                fma2(acc2[r], a1.x, w2[2]); fma2(acc2[r], a1.y, w2[3]);
                fma2(acc2[r], a2.x, w2[4]); fma2(acc2[r], a2.y, w2[5]);
                fma2(acc2[r], a3.x, w2[6]); fma2(acc2[r], a3.y, w2[7]);
            }
        }
        // epilogue: reduce pair-sums, add bias, park in xg (writer == reader)
        float bsum = bih[tid] + bhh[tid];
        #pragma unroll
        for (int r = 0; r < RR; ++r) {
            float lo, hi; unpack2(acc2[r], lo, hi);
            xg[r * GG + tid] = lo + hi + bsum;
        }
    }

    // =========== fused backward single step ===========
    // Backward stream runs exactly one step from h0=c0=0, so Whh_b and the
    // forget gate vanish: h_b = sig(o) * tanh( sig(i) * tanh(g) ) from
    // gates = x[:,K-1] @ Wihb^T + bihb + bhhb.  Skip f-gate columns.
    if ((tid >> 6) != 1) {
        u64 ab2[BF] = {0ull, 0ull, 0ull, 0ull};
        const float* wbrow = Wihb + tid * FF;
        #pragma unroll 1
        for (int cc = 0; cc < 8; ++cc) {
            const int f0 = cc * 16;
            u64 w2[8];
            #pragma unroll
            for (int q = 0; q < 4; ++q) {
                ulonglong2 t = reinterpret_cast<const ulonglong2*>(wbrow + f0)[q];
                w2[2 * q] = t.x; w2[2 * q + 1] = t.y;
            }
            #pragma unroll
            for (int b = 0; b < BF; ++b) {
                const ulonglong2* xp = reinterpret_cast<const ulonglong2*>(
                    x_s + (b * KK + (KK - 1)) * FF + f0);
                ulonglong2 a0 = xp[0], a1 = xp[1], a2 = xp[2], a3 = xp[3];
                fma2(ab2[b], a0.x, w2[0]); fma2(ab2[b], a0.y, w2[1]);
                fma2(ab2[b], a1.x, w2[2]); fma2(ab2[b], a1.y, w2[3]);
                fma2(ab2[b], a2.x, w2[4]); fma2(ab2[b], a2.y, w2[5]);
                fma2(ab2[b], a3.x, w2[6]); fma2(ab2[b], a3.y, w2[7]);
            }
        }
        float bsb = bihb[tid] + bhhb[tid];
        #pragma unroll
        for (int b = 0; b < BF; ++b) {
            float lo, hi; unpack2(ab2[b], lo, hi);
            gates[b * GG + tid] = lo + hi + bsb;
        }
    }
    __syncthreads();

    // backward activation: thread owns (node cb, cell cj); write out[:,64:128]
    const int cb = tid >> 6, cj = tid & 63;
    {
        float gi = gates[cb * GG +       cj];
        float gg = gates[cb * GG + 128 + cj];
        float go = gates[cb * GG + 192 + cj];
        float cv = sigf(gi) * tanh_fast(gg);
        out[(n0 + cb) * (2 * HH) + HH + cj] = sigf(go) * tanh_fast(cv);
    }

    // ---- register-cache this thread's Whh row as 32 packed pairs ----
    u64 wpair[32];
    {
        const ulonglong2* hrow =
            reinterpret_cast<const ulonglong2*>(Whh + tid * HH);
        #pragma unroll
        for (int q = 0; q < 16; ++q) {
            ulonglong2 t = hrow[q];
            wpair[2 * q] = t.x; wpair[2 * q + 1] = t.y;
        }
    }
    __syncthreads();   // backward reads of gates done -> reuse for recurrence

    // =========== forward recurrence: 10 steps ===========
    float cst = 0.0f, hout = 0.0f;

    #pragma unroll 1
    for (int k = 0; k < KK; ++k) {
        // col phase: thread computes gate col c=tid for all 4 nodes
        float gv[BF];
        #pragma unroll
        for (int b = 0; b < BF; ++b) {
            float g = xg[(b * KK + k) * GG + tid];
            if (k > 0) {
                u64 s2 = 0ull;
                const ulonglong2* h2 =
                    reinterpret_cast<const ulonglong2*>(h_s + b * HH);
                #pragma unroll
                for (int q = 0; q < 16; ++q) {
                    ulonglong2 hv = h2[q];          // warp-broadcast
                    fma2(s2, hv.x, wpair[2 * q]);
                    fma2(s2, hv.y, wpair[2 * q + 1]);
                }
                float lo, hi; unpack2(s2, lo, hi);
                g += lo + hi;
            }
            gv[b] = g;
        }
        #pragma unroll
        for (int b = 0; b < BF; ++b) gates[b * GG + tid] = gv[b];
        __syncthreads();

        // cell phase: thread owns cell (cb, cj)
        {
            float gi = gates[cb * GG +       cj];
            float gf = gates[cb * GG +  64 + cj];
            float gg = gates[cb * GG + 128 + cj];
            float go = gates[cb * GG + 192 + cj];
            float iv = sigf(gi), fv = sigf(gf);
            float gvv = tanh_fast(gg), ov = sigf(go);
            cst  = (k == 0) ? iv * gvv : fmaf(fv, cst, iv * gvv);
            hout = ov * tanh_fast(cst);
            h_s[cb * HH + cj] = hout;
        }
        __syncthreads();
    }

    // ---- write h_f into out[:, 0:64] ----
    out[(n0 + cb) * (2 * HH) + cj] = hout;
}

// ============================================================================
// Launch
// ============================================================================
extern "C" void kernel_launch(void* const* d_in, const int* in_sizes, int n_in,
                              void* d_out, int out_size)
{
    const int*   nidx  = (const int*)  d_in[0];
    const float* embed = (const float*)d_in[1];
    const float* Wih_f = (const float*)d_in[2];
    const float* Whh_f = (const float*)d_in[3];
    const float* bih_f = (const float*)d_in[4];
    const float* bhh_f = (const float*)d_in[5];
    const float* Wih_b = (const float*)d_in[6];
    // d_in[7] = Whh_b: provably unused (single backward step from h0 = 0)
    const float* bih_b = (const float*)d_in[8];
    const float* bhh_b = (const float*)d_in[9];
    float* out = (float*)d_out;

    const size_t smem = SM_FLOATS * sizeof(float);  // 66560 B
    cudaFuncSetAttribute(lstm_kernel,
                         cudaFuncAttributeMaxDynamicSharedMemorySize, (int)smem);

    lstm_kernel<<<NN / BF, 256, smem>>>(nidx, embed,
                                        Wih_f, Whh_f, bih_f, bhh_f,
                                        Wih_b, bih_b, bhh_b, out);
}

// round 9
// speedup vs baseline: 1.1434x; 1.1430x over previous
#include <cuda_runtime.h>

// Problem constants
#define NN 50000   // nodes
#define KK 10      // sampled neighbors per node
#define FF 128     // embedding dim
#define HH 64      // hidden per direction
#define GG 256     // 4*H gate width
#define BF 4       // nodes per CTA
#define RR 40      // BF*KK rows per CTA
#define NT 256     // threads per CTA

// smem strides (floats)
#define XS   132   // x_s row stride (16B-aligned, CF 4-row reads)
#define WSTS 36    // staged-W row stride (16B-aligned)
#define XGS  260   // xg / gates row stride
#define HS   68    // h_s row stride

// smem offsets (floats)
#define OFF_X    0        // x_s   [40][132]  = 5280
#define OFF_WST  5280     // wst   [256][36]  = 9216
#define OFF_XG   14496    // xg    [40][260]  = 10400
#define OFF_GT   24896    // gates [4][260]   = 1040
#define OFF_H    25936    // h_s   [4][68]    = 272
#define SM_FLOATS 26208   // 104832 bytes -> 2 CTAs/SM

typedef unsigned long long u64;

// ---------------- packed f32x2 helpers (sm_103a FFMA2 path) ----------------
__device__ __forceinline__ void fma2(u64& d, u64 a, u64 b) {
    asm("fma.rn.f32x2 %0, %1, %2, %0;" : "+l"(d) : "l"(a), "l"(b));
}
__device__ __forceinline__ void unpack2(u64 v, float& lo, float& hi) {
    unsigned a, b;
    asm("mov.b64 {%0, %1}, %2;" : "=r"(a), "=r"(b) : "l"(v));
    lo = __uint_as_float(a); hi = __uint_as_float(b);
}

// ---------------- transcendentals (fast, ~1e-6; tolerance is 1e-3) ---------
__device__ __forceinline__ float sigf(float x) {
    return __fdividef(1.0f, 1.0f + __expf(-x));
}
__device__ __forceinline__ float tanh_fast(float x) {
    x = fminf(fmaxf(x, -9.0f), 9.0f);
    float e = __expf(-2.0f * x);
    return __fdividef(1.0f - e, 1.0f + e);
}

__global__ __launch_bounds__(NT, 2)
void lstm_kernel(const int*   __restrict__ nidx,
                 const float* __restrict__ embed,
                 const float* __restrict__ Wih,
                 const float* __restrict__ Whh,
                 const float* __restrict__ bih,
                 const float* __restrict__ bhh,
                 const float* __restrict__ Wihb,
                 const float* __restrict__ bihb,
                 const float* __restrict__ bhhb,
                 float*       __restrict__ out)
{
    extern __shared__ float sm[];
    float* x_s   = sm + OFF_X;
    float* wst   = sm + OFF_WST;
    float* xg    = sm + OFF_XG;
    float* gates = sm + OFF_GT;
    float* h_s   = sm + OFF_H;

    const int tid  = threadIdx.x;
    const int lane = tid & 31;
    const int wrp  = tid >> 5;
    const int rg   = lane >> 3;          // row group 0..3
    const int cq   = lane & 7;           // col phase 0..7
    const int c0   = wrp * 32 + cq;      // thread cols: c0 + 8j, j=0..3
    const int n0   = blockIdx.x * BF;

    // ---- gather embeddings: warp w loads rows w+8i (row = node*KK + k) ----
    #pragma unroll
    for (int i = 0; i < 5; ++i) {
        int row = wrp + 8 * i;
        int idx = nidx[n0 * KK + row];                 // uniform per warp
        float4 v = reinterpret_cast<const float4*>(embed)[idx * (FF / 4) + lane];
        *reinterpret_cast<float4*>(&x_s[row * XS + lane * 4]) = v;
    }
    __syncthreads();

    // =========== forward input-projection GEMM (strip-tiled, FMA2) ===========
    u64 acc[10][4];
    #pragma unroll
    for (int m = 0; m < 10; ++m)
        #pragma unroll
        for (int j = 0; j < 4; ++j) acc[m][j] = 0ull;

    #pragma unroll 1
    for (int fc = 0; fc < 4; ++fc) {
        // stage Wih f-chunk [256 cols][32 f] -> wst (4-line coalesced LDG.128)
        #pragma unroll
        for (int i = 0; i < 8; ++i) {
            int p = tid + NT * i;                      // p in [0, 2048)
            int c = p >> 3, q = p & 7;
            float4 v = reinterpret_cast<const float4*>(Wih)[c * 32 + fc * 8 + q];
            *reinterpret_cast<float4*>(&wst[c * WSTS + q * 4]) = v;
        }
        __syncthreads();

        #pragma unroll
        for (int f4 = 0; f4 < 8; ++f4) {
            const int lf0 = f4 * 4;
            u64 wlo[4], whi[4];
            #pragma unroll
            for (int j = 0; j < 4; ++j) {              // 8 distinct cols/warp
                ulonglong2 t = *reinterpret_cast<const ulonglong2*>(
                    &wst[(c0 + 8 * j) * WSTS + lf0]);
                wlo[j] = t.x; whi[j] = t.y;
            }
            #pragma unroll
            for (int m = 0; m < 10; ++m) {             // 4 distinct rows/warp
                ulonglong2 xv = *reinterpret_cast<const ulonglong2*>(
                    &x_s[(rg + 4 * m) * XS + fc * 32 + lf0]);
                #pragma unroll
                for (int j = 0; j < 4; ++j) {
                    fma2(acc[m][j], xv.x, wlo[j]);
                    fma2(acc[m][j], xv.y, whi[j]);
                }
            }
        }
        __syncthreads();
    }

    // ---- epilogue: reduce pair-sums, add bias, park in xg ----
    {
        float bs[4];
        #pragma unroll
        for (int j = 0; j < 4; ++j) bs[j] = bih[c0 + 8 * j] + bhh[c0 + 8 * j];
        #pragma unroll
        for (int m = 0; m < 10; ++m)
            #pragma unroll
            for (int j = 0; j < 4; ++j) {
                float lo, hi; unpack2(acc[m][j], lo, hi);
                xg[(rg + 4 * m) * XGS + c0 + 8 * j] = lo + hi + bs[j];
            }
    }

    // =========== fused backward single step ===========
    // Backward stream runs exactly one step from h0=c0=0, so Whh_b and the
    // forget gate vanish: h_b = sig(o)*tanh( sig(i)*tanh(g) ) from
    // gates_b = x[:,K-1] @ Wihb^T + bihb + bhhb. Skip f-gate columns.
    {
        const int ac = (tid < 192) ? (tid < 64 ? tid : tid + 64) : -1;
        u64 bacc[BF] = {0ull, 0ull, 0ull, 0ull};

        #pragma unroll 1
        for (int fc = 0; fc < 4; ++fc) {
            #pragma unroll
            for (int i = 0; i < 8; ++i) {
                int p = tid + NT * i;
                int c = p >> 3, q = p & 7;
                float4 v = reinterpret_cast<const float4*>(Wihb)[c * 32 + fc * 8 + q];
                *reinterpret_cast<float4*>(&wst[c * WSTS + q * 4]) = v;
            }
            __syncthreads();
            if (ac >= 0) {
                #pragma unroll
                for (int f4 = 0; f4 < 8; ++f4) {
                    ulonglong2 wv = *reinterpret_cast<const ulonglong2*>(
                        &wst[ac * WSTS + f4 * 4]);
                    #pragma unroll
                    for (int b = 0; b < BF; ++b) {
                        ulonglong2 xv = *reinterpret_cast<const ulonglong2*>(
                            &x_s[(b * KK + KK - 1) * XS + fc * 32 + f4 * 4]);
                        fma2(bacc[b], xv.x, wv.x);
                        fma2(bacc[b], xv.y, wv.y);
                    }
                }
            }
            __syncthreads();
        }
        if (ac >= 0) {
            float bsb = bihb[ac] + bhhb[ac];
            #pragma unroll
            for (int b = 0; b < BF; ++b) {
                float lo, hi; unpack2(bacc[b], lo, hi);
                gates[b * XGS + ac] = lo + hi + bsb;
            }
        }
    }
    __syncthreads();

    // backward activation: thread = (node cb, cell cj); write out[:, 64:128]
    const int cb = tid >> 6, cj = tid & 63;
    {
        float gi = gates[cb * XGS +       cj];
        float gg = gates[cb * XGS + 128 + cj];
        float go = gates[cb * XGS + 192 + cj];
        float cv = sigf(gi) * tanh_fast(gg);
        out[(n0 + cb) * (2 * HH) + HH + cj] = sigf(go) * tanh_fast(cv);
    }

    // ---- register-cache this thread's Whh row (col = tid) as 32 pairs ----
    u64 wpair[32];
    {
        const ulonglong2* hrow =
            reinterpret_cast<const ulonglong2*>(Whh + tid * HH);
        #pragma unroll
        for (int q = 0; q < 16; ++q) {
            ulonglong2 t = hrow[q];
            wpair[2 * q] = t.x; wpair[2 * q + 1] = t.y;
        }
    }
    __syncthreads();   // backward gate reads done -> reuse gates buffer

    // =========== forward recurrence: 10 steps ===========
    float cst = 0.0f, hout = 0.0f;

    #pragma unroll 1
    for (int k = 0; k < KK; ++k) {
        // col phase: thread computes gate col c = tid for all 4 nodes
        float gv[BF];
        #pragma unroll
        for (int b = 0; b < BF; ++b) {
            float g = xg[(b * KK + k) * XGS + tid];
            if (k > 0) {
                u64 s2 = 0ull;
                const ulonglong2* h2 =
                    reinterpret_cast<const ulonglong2*>(&h_s[b * HS]);
                #pragma unroll
                for (int q = 0; q < 16; ++q) {
                    ulonglong2 hv = h2[q];             // warp-broadcast
                    fma2(s2, hv.x, wpair[2 * q]);
                    fma2(s2, hv.y, wpair[2 * q + 1]);
                }
                float lo, hi; unpack2(s2, lo, hi);
                g += lo + hi;
            }
            gv[b] = g;
        }
        #pragma unroll
        for (int b = 0; b < BF; ++b) gates[b * XGS + tid] = gv[b];
        __syncthreads();

        // cell phase: thread owns cell (cb, cj)
        {
            float gi = gates[cb * XGS +       cj];
            float gf = gates[cb * XGS +  64 + cj];
            float gg = gates[cb * XGS + 128 + cj];
            float go = gates[cb * XGS + 192 + cj];
            float iv = sigf(gi), fv = sigf(gf);
            float gvv = tanh_fast(gg), ov = sigf(go);
            cst  = (k == 0) ? iv * gvv : fmaf(fv, cst, iv * gvv);
            hout = ov * tanh_fast(cst);
            h_s[cb * HS + cj] = hout;
        }
        __syncthreads();
    }

    // ---- write h_f into out[:, 0:64] ----
    out[(n0 + cb) * (2 * HH) + cj] = hout;
}

// ============================================================================
// Launch
// ============================================================================
extern "C" void kernel_launch(void* const* d_in, const int* in_sizes, int n_in,
                              void* d_out, int out_size)
{
    const int*   nidx  = (const int*)  d_in[0];
    const float* embed = (const float*)d_in[1];
    const float* Wih_f = (const float*)d_in[2];
    const float* Whh_f = (const float*)d_in[3];
    const float* bih_f = (const float*)d_in[4];
    const float* bhh_f = (const float*)d_in[5];
    const float* Wih_b = (const float*)d_in[6];
    // d_in[7] = Whh_b: provably unused (single backward step from h0 = 0)
    const float* bih_b = (const float*)d_in[8];
    const float* bhh_b = (const float*)d_in[9];
    float* out = (float*)d_out;

    const size_t smem = SM_FLOATS * sizeof(float);  // 104832 B -> 2 CTAs/SM
    cudaFuncSetAttribute(lstm_kernel,
                         cudaFuncAttributeMaxDynamicSharedMemorySize, (int)smem);

    lstm_kernel<<<NN / BF, NT, smem>>>(nidx, embed,
                                       Wih_f, Whh_f, bih_f, bhh_f,
                                       Wih_b, bih_b, bhh_b, out);
}

// round 13
// speedup vs baseline: 1.3384x; 1.1706x over previous
#include <cuda_runtime.h>

// Problem constants
#define NN 50000   // nodes
#define KK 10      // sampled neighbors per node
#define FF 128     // embedding dim
#define HH 64      // hidden per direction
#define GG 256     // 4*H gate width
#define BF 4       // nodes per CTA
#define NT 256     // threads per CTA

// smem float offsets
#define OFF_X    0          // x_s   [40][128] = 5120
#define OFF_CHK  5120       // chunk [32][258] = 8256
#define OFF_GT   5120       // overlay: gates [4][256] = 1024
#define OFF_H    6144       // overlay: h_s   [4][64]  = 256
#define OFF_XG   13376      // xg    [40][256] = 10240
#define SM_FLOATS 23616     // 94464 bytes -> 2 CTAs/SM

typedef unsigned long long u64;

// ---------------- packed f32x2 helpers (sm_103a FFMA2 path) ----------------
__device__ __forceinline__ void fma2(u64& d, u64 a, u64 b) {
    asm("fma.rn.f32x2 %0, %1, %2, %0;" : "+l"(d) : "l"(a), "l"(b));
}
__device__ __forceinline__ u64 add2(u64 a, u64 b) {
    u64 d; asm("add.rn.f32x2 %0, %1, %2;" : "=l"(d) : "l"(a), "l"(b)); return d;
}
__device__ __forceinline__ u64 pack2(float lo, float hi) {
    u64 d;
    asm("mov.b64 %0, {%1, %2};" : "=l"(d)
        : "r"(__float_as_uint(lo)), "r"(__float_as_uint(hi)));
    return d;
}
__device__ __forceinline__ void unpack2(u64 v, float& lo, float& hi) {
    unsigned a, b;
    asm("mov.b64 {%0, %1}, %2;" : "=r"(a), "=r"(b) : "l"(v));
    lo = __uint_as_float(a); hi = __uint_as_float(b);
}

// ---------------- transcendentals (fast, ~1e-6; tolerance is 1e-3) ---------
__device__ __forceinline__ float sigf(float x) {
    return __fdividef(1.0f, 1.0f + __expf(-x));
}
__device__ __forceinline__ float tanh_fast(float x) {
    x = fminf(fmaxf(x, -9.0f), 9.0f);
    float e = __expf(-2.0f * x);
    return __fdividef(1.0f - e, 1.0f + e);
}

// ============================================================================
// One fused kernel, 2 CTAs/SM (16 warps). CTA = 4 nodes, 256 threads.
// GEMM: warp pair (2b, 2b+1) owns node b; warp half rho splits neighbors
//       k = rho*5 + m. Thread owns col-pairs c = 2*lane + 64*j (j = gate).
// Recurrence: R3 scheme — thread owns gate col c = tid across 4 nodes,
//       Whh row reg-cached as packed pairs, h read as broadcast LDS.128.
// Backward: single step from h0=c0=0 (Whh_b + f-gate provably dead),
//       thread-per-cell scalar dot products from the staged Wihb chunk.
// ============================================================================
__global__ __launch_bounds__(NT, 2)
void lstm_kernel(const int*   __restrict__ nidx,
                 const float* __restrict__ embed,
                 const float* __restrict__ Wih,
                 const float* __restrict__ Whh,
                 const float* __restrict__ bih,
                 const float* __restrict__ bhh,
                 const float* __restrict__ Wihb,
                 const float* __restrict__ bihb,
                 const float* __restrict__ bhhb,
                 float*       __restrict__ out)
{
    extern __shared__ float sm[];
    float* x_s   = sm + OFF_X;
    float* chunk = sm + OFF_CHK;
    float* gates = sm + OFF_GT;    // overlays chunk (dead after backward)
    float* h_s   = sm + OFF_H;     // overlays chunk
    float* xg    = sm + OFF_XG;

    const int tid  = threadIdx.x;
    const int lane = tid & 31;
    const int wrp  = tid >> 5;
    const int node = wrp >> 1;     // GEMM node for this warp
    const int rho  = wrp & 1;      // neighbor-half split
    const int n0   = blockIdx.x * BF;

    // ---- gather: warp w loads rows w + 8i (row = node*KK + k), float4 ----
    #pragma unroll
    for (int i = 0; i < 5; ++i) {
        int row = wrp + 8 * i;
        int idx = nidx[n0 * KK + row];                 // uniform per warp
        float4 v = reinterpret_cast<const float4*>(embed)[idx * (FF / 4) + lane];
        *reinterpret_cast<float4*>(&x_s[row * FF + lane * 4]) = v;
    }
    __syncthreads();

    // =========== forward input-projection GEMM (chunked, FMA2) ===========
    // acc[m][j]: col pair (2*lane+64j, +1) for neighbor k = rho*5+m of node.
    u64 acc[5][4];
    #pragma unroll
    for (int m = 0; m < 5; ++m)
        #pragma unroll
        for (int j = 0; j < 4; ++j) acc[m][j] = 0ull;

    #pragma unroll 1
    for (int cc = 0; cc < 4; ++cc) {
        const int f0 = cc * 32;
        // stage chunk[ff][c] = Wih[c][f0+ff]  (coalesced LDG, 2-way STS)
        #pragma unroll 8
        for (int r = 0; r < 32; ++r) {
            int c = wrp * 32 + r;
            chunk[lane * 258 + c] = Wih[c * FF + f0 + lane];
        }
        __syncthreads();

        #pragma unroll
        for (int ff4 = 0; ff4 < 8; ++ff4) {
            float4 a4[5];
            #pragma unroll
            for (int m = 0; m < 5; ++m)
                a4[m] = *reinterpret_cast<const float4*>(
                    &x_s[(node * KK + rho * 5 + m) * FF + f0 + ff4 * 4]);
            #pragma unroll
            for (int u = 0; u < 4; ++u) {
                u64 w2[4];
                const float* crow = &chunk[(ff4 * 4 + u) * 258 + 2 * lane];
                #pragma unroll
                for (int j = 0; j < 4; ++j)
                    w2[j] = *reinterpret_cast<const u64*>(crow + 64 * j);
                #pragma unroll
                for (int m = 0; m < 5; ++m) {
                    float av = (u == 0) ? a4[m].x : (u == 1) ? a4[m].y
                             : (u == 2) ? a4[m].z : a4[m].w;
                    u64 av2 = pack2(av, av);
                    #pragma unroll
                    for (int j = 0; j < 4; ++j) fma2(acc[m][j], av2, w2[j]);
                }
            }
        }
        __syncthreads();
    }

    // ---- epilogue: packed bias add, park in xg as u64 pairs ----
    {
        u64 bs2[4];
        #pragma unroll
        for (int j = 0; j < 4; ++j) {
            int c = 2 * lane + 64 * j;
            bs2[j] = add2(*reinterpret_cast<const u64*>(bih + c),
                          *reinterpret_cast<const u64*>(bhh + c));
        }
        #pragma unroll
        for (int m = 0; m < 5; ++m)
            #pragma unroll
            for (int j = 0; j < 4; ++j)
                *reinterpret_cast<u64*>(
                    &xg[(node * KK + rho * 5 + m) * GG + 2 * lane + 64 * j])
                    = add2(acc[m][j], bs2[j]);
    }

    // =========== fused backward single step (thread-per-cell) ===========
    // h_b = sig(i)*tanh(g) -> c, then sig(o)*tanh(c): gates from
    // x[:,K-1] @ Wihb^T + bihb + bhhb.
    const int cb = tid >> 6, cj = tid & 63;
    {
        float bi = 0.0f, bg = 0.0f, bo = 0.0f;
        #pragma unroll 1
        for (int cc = 0; cc < 4; ++cc) {
            const int f0 = cc * 32;
            #pragma unroll 8
            for (int r = 0; r < 32; ++r) {
                int c = wrp * 32 + r;
                chunk[lane * 258 + c] = Wihb[c * FF + f0 + lane];
            }
            __syncthreads();
            const float* xr = &x_s[(cb * KK + KK - 1) * FF + f0];
            #pragma unroll 8
            for (int ff = 0; ff < 32; ++ff) {
                float xv = xr[ff];                     // uniform per warp
                const float* cr = &chunk[ff * 258 + cj];
                bi = fmaf(xv, cr[0],   bi);            // i gate
                bg = fmaf(xv, cr[128], bg);            // g gate
                bo = fmaf(xv, cr[192], bo);            // o gate
            }
            __syncthreads();
        }
        bi += bihb[cj]       + bhhb[cj];
        bg += bihb[128 + cj] + bhhb[128 + cj];
        bo += bihb[192 + cj] + bhhb[192 + cj];
        float cv = sigf(bi) * tanh_fast(bg);
        out[(n0 + cb) * (2 * HH) + HH + cj] = sigf(bo) * tanh_fast(cv);
    }

    // ---- register-cache this thread's Whh row (col = tid) as 32 pairs ----
    u64 wpair[32];
    {
        const ulonglong2* hrow =
            reinterpret_cast<const ulonglong2*>(Whh + tid * HH);
        #pragma unroll
        for (int q = 0; q < 16; ++q) {
            ulonglong2 t = hrow[q];
            wpair[2 * q] = t.x; wpair[2 * q + 1] = t.y;
        }
    }
    __syncthreads();   // chunk fully dead -> gates/h_s overlay safe

    // =========== forward recurrence: 10 steps ===========
    float cst = 0.0f, hout = 0.0f;

    #pragma unroll 1
    for (int k = 0; k < KK; ++k) {
        // col phase: thread computes gate col c = tid for all 4 nodes
        float gv[BF];
        #pragma unroll
        for (int b = 0; b < BF; ++b) {
            float g = xg[(b * KK + k) * GG + tid];
            if (k > 0) {
                u64 s2 = 0ull;
                const ulonglong2* h2 =
                    reinterpret_cast<const ulonglong2*>(&h_s[b * HH]);
                #pragma unroll
                for (int q = 0; q < 16; ++q) {
                    ulonglong2 hv = h2[q];             // warp-broadcast
                    fma2(s2, hv.x, wpair[2 * q]);
                    fma2(s2, hv.y, wpair[2 * q + 1]);
                }
                float lo, hi; unpack2(s2, lo, hi);
                g += lo + hi;
            }
            gv[b] = g;
        }
        #pragma unroll
        for (int b = 0; b < BF; ++b) gates[b * GG + tid] = gv[b];
        __syncthreads();

        // cell phase: thread owns cell (cb, cj)
        {
            float gi = gates[cb * GG +       cj];
            float gf = gates[cb * GG +  64 + cj];
            float gg = gates[cb * GG + 128 + cj];
            float go = gates[cb * GG + 192 + cj];
            float iv = sigf(gi), fv = sigf(gf);
            float gvv = tanh_fast(gg), ov = sigf(go);
            cst  = (k == 0) ? iv * gvv : fmaf(fv, cst, iv * gvv);
            hout = ov * tanh_fast(cst);
            h_s[cb * HH + cj] = hout;
        }
        __syncthreads();
    }

    // ---- write h_f into out[:, 0:64] ----
    out[(n0 + cb) * (2 * HH) + cj] = hout;
}

// ============================================================================
// Launch
// ============================================================================
extern "C" void kernel_launch(void* const* d_in, const int* in_sizes, int n_in,
                              void* d_out, int out_size)
{
    const int*   nidx  = (const int*)  d_in[0];
    const float* embed = (const float*)d_in[1];
    const float* Wih_f = (const float*)d_in[2];
    const float* Whh_f = (const float*)d_in[3];
    const float* bih_f = (const float*)d_in[4];
    const float* bhh_f = (const float*)d_in[5];
    const float* Wih_b = (const float*)d_in[6];
    // d_in[7] = Whh_b: provably unused (single backward step from h0 = 0)
    const float* bih_b = (const float*)d_in[8];
    const float* bhh_b = (const float*)d_in[9];
    float* out = (float*)d_out;

    const size_t smem = SM_FLOATS * sizeof(float);  // 94464 B -> 2 CTAs/SM
    cudaFuncSetAttribute(lstm_kernel,
                         cudaFuncAttributeMaxDynamicSharedMemorySize, (int)smem);

    lstm_kernel<<<NN / BF, NT, smem>>>(nidx, embed,
                                       Wih_f, Whh_f, bih_f, bhh_f,
                                       Wih_b, bih_b, bhh_b, out);
}

// round 15
// speedup vs baseline: 1.3628x; 1.0182x over previous
#include <cuda_runtime.h>

// Problem constants
#define NN 50000   // nodes
#define KK 10      // sampled neighbors per node
#define FF 128     // embedding dim
#define HH 64      // hidden per direction
#define GG 256     // 4*H gate width
#define BF 4       // nodes per CTA
#define NT 256     // threads per CTA

// smem float offsets
#define OFF_X    0          // x_s   [40][128] = 5120
#define OFF_CHK  5120       // chunk [32][258] = 8256
#define OFF_GT   5120       // overlay: gates [4][256] = 1024
#define OFF_H    6144       // overlay: h_s   [4][64]  = 256
#define OFF_XG   13376      // xg    [40][256] = 10240
#define SM_FLOATS 23616     // 94464 bytes -> 2 CTAs/SM

typedef unsigned long long u64;

// ---------------- packed f32x2 helpers (sm_103a FFMA2 path) ----------------
__device__ __forceinline__ void fma2(u64& d, u64 a, u64 b) {
    asm("fma.rn.f32x2 %0, %1, %2, %0;" : "+l"(d) : "l"(a), "l"(b));
}
__device__ __forceinline__ u64 add2(u64 a, u64 b) {
    u64 d; asm("add.rn.f32x2 %0, %1, %2;" : "=l"(d) : "l"(a), "l"(b)); return d;
}
__device__ __forceinline__ u64 pack2(float lo, float hi) {
    u64 d;
    asm("mov.b64 %0, {%1, %2};" : "=l"(d)
        : "r"(__float_as_uint(lo)), "r"(__float_as_uint(hi)));
    return d;
}
__device__ __forceinline__ void unpack2(u64 v, float& lo, float& hi) {
    unsigned a, b;
    asm("mov.b64 {%0, %1}, %2;" : "=r"(a), "=r"(b) : "l"(v));
    lo = __uint_as_float(a); hi = __uint_as_float(b);
}

// ---------------- transcendentals (fast, ~1e-6; tolerance is 1e-3) ---------
__device__ __forceinline__ float sigf(float x) {
    return __fdividef(1.0f, 1.0f + __expf(-x));
}
__device__ __forceinline__ float tanh_fast(float x) {
    x = fminf(fmaxf(x, -9.0f), 9.0f);
    float e = __expf(-2.0f * x);
    return __fdividef(1.0f - e, 1.0f + e);
}

// ============================================================================
// One fused kernel, 2 CTAs/SM (16 warps). CTA = 4 nodes, 256 threads.
// GEMM: warp w owns node (w&3), col half ch=(w>>2); thread owns col-pairs
//       c = 128*ch + 2*lane + 64*j (j=0,1) across ALL 10 neighbor rows.
//       -> each w-pair LDS.64 is reused by 10 rows (2x the reuse of R13),
//          halving the dominant smem read stream.
// Recurrence: thread owns gate col c = tid across 4 nodes, Whh row
//       reg-cached as packed pairs, h read as broadcast LDS.128.
// Backward: single step from h0=c0=0 (Whh_b + f-gate provably dead),
//       thread-per-cell scalar dot products from the staged Wihb chunk.
// ============================================================================
__global__ __launch_bounds__(NT, 2)
void lstm_kernel(const int*   __restrict__ nidx,
                 const float* __restrict__ embed,
                 const float* __restrict__ Wih,
                 const float* __restrict__ Whh,
                 const float* __restrict__ bih,
                 const float* __restrict__ bhh,
                 const float* __restrict__ Wihb,
                 const float* __restrict__ bihb,
                 const float* __restrict__ bhhb,
                 float*       __restrict__ out)
{
    extern __shared__ float sm[];
    float* x_s   = sm + OFF_X;
    float* chunk = sm + OFF_CHK;
    float* gates = sm + OFF_GT;    // overlays chunk (dead after backward)
    float* h_s   = sm + OFF_H;     // overlays chunk
    float* xg    = sm + OFF_XG;

    const int tid  = threadIdx.x;
    const int lane = tid & 31;
    const int wrp  = tid >> 5;
    const int node = wrp & 3;      // GEMM node for this warp
    const int ch   = wrp >> 2;     // column half (0: cols 0..127, 1: 128..255)
    const int cbase = 128 * ch + 2 * lane;   // thread col pairs: cbase + 64*j
    const int n0   = blockIdx.x * BF;

    // ---- gather: warp w loads rows w + 8i (row = node*KK + k), float4 ----
    #pragma unroll
    for (int i = 0; i < 5; ++i) {
        int row = wrp + 8 * i;
        int idx = nidx[n0 * KK + row];                 // uniform per warp
        float4 v = reinterpret_cast<const float4*>(embed)[idx * (FF / 4) + lane];
        *reinterpret_cast<float4*>(&x_s[row * FF + lane * 4]) = v;
    }
    __syncthreads();

    // =========== forward input-projection GEMM (chunked, FMA2) ===========
    // acc[m][j]: col pair (cbase+64j, +1) for neighbor m of node.
    u64 acc[KK][2];
    #pragma unroll
    for (int m = 0; m < KK; ++m) { acc[m][0] = 0ull; acc[m][1] = 0ull; }

    #pragma unroll 1
    for (int cc = 0; cc < 4; ++cc) {
        const int f0 = cc * 32;
        // stage chunk[ff][c] = Wih[c][f0+ff]  (coalesced LDG, 2-way STS)
        #pragma unroll 8
        for (int r = 0; r < 32; ++r) {
            int c = wrp * 32 + r;
            chunk[lane * 258 + c] = Wih[c * FF + f0 + lane];
        }
        __syncthreads();

        #pragma unroll
        for (int ff4 = 0; ff4 < 8; ++ff4) {
            float4 a4[KK];
            #pragma unroll
            for (int m = 0; m < KK; ++m)
                a4[m] = *reinterpret_cast<const float4*>(
                    &x_s[(node * KK + m) * FF + f0 + ff4 * 4]);
            #pragma unroll
            for (int u = 0; u < 4; ++u) {
                const float* crow = &chunk[(ff4 * 4 + u) * 258 + cbase];
                u64 w0 = *reinterpret_cast<const u64*>(crow);
                u64 w1 = *reinterpret_cast<const u64*>(crow + 64);
                #pragma unroll
                for (int m = 0; m < KK; ++m) {
                    float av = (u == 0) ? a4[m].x : (u == 1) ? a4[m].y
                             : (u == 2) ? a4[m].z : a4[m].w;
                    u64 av2 = pack2(av, av);
                    fma2(acc[m][0], av2, w0);
                    fma2(acc[m][1], av2, w1);
                }
            }
        }
        __syncthreads();
    }

    // ---- epilogue: packed bias add, park in xg as u64 pairs ----
    {
        u64 bs0 = add2(*reinterpret_cast<const u64*>(bih + cbase),
                       *reinterpret_cast<const u64*>(bhh + cbase));
        u64 bs1 = add2(*reinterpret_cast<const u64*>(bih + cbase + 64),
                       *reinterpret_cast<const u64*>(bhh + cbase + 64));
        #pragma unroll
        for (int m = 0; m < KK; ++m) {
            *reinterpret_cast<u64*>(&xg[(node * KK + m) * GG + cbase])
                = add2(acc[m][0], bs0);
            *reinterpret_cast<u64*>(&xg[(node * KK + m) * GG + cbase + 64])
                = add2(acc[m][1], bs1);
        }
    }

    // =========== fused backward single step (thread-per-cell) ===========
    // h_b = sig(o)*tanh( sig(i)*tanh(g) ): gates from
    // x[:,K-1] @ Wihb^T + bihb + bhhb (Whh_b and f-gate provably dead).
    const int cb = tid >> 6, cj = tid & 63;
    {
        float bi = 0.0f, bg = 0.0f, bo = 0.0f;
        #pragma unroll 1
        for (int cc = 0; cc < 4; ++cc) {
            const int f0 = cc * 32;
            #pragma unroll 8
            for (int r = 0; r < 32; ++r) {
                int c = wrp * 32 + r;
                chunk[lane * 258 + c] = Wihb[c * FF + f0 + lane];
            }
            __syncthreads();
            const float* xr = &x_s[(cb * KK + KK - 1) * FF + f0];
            #pragma unroll 8
            for (int ff = 0; ff < 32; ++ff) {
                float xv = xr[ff];                     // uniform per warp
                const float* cr = &chunk[ff * 258 + cj];
                bi = fmaf(xv, cr[0],   bi);            // i gate
                bg = fmaf(xv, cr[128], bg);            // g gate
                bo = fmaf(xv, cr[192], bo);            // o gate
            }
            __syncthreads();
        }
        bi += bihb[cj]       + bhhb[cj];
        bg += bihb[128 + cj] + bhhb[128 + cj];
        bo += bihb[192 + cj] + bhhb[192 + cj];
        float cv = sigf(bi) * tanh_fast(bg);
        out[(n0 + cb) * (2 * HH) + HH + cj] = sigf(bo) * tanh_fast(cv);
    }

    // ---- register-cache this thread's Whh row (col = tid) as 32 pairs ----
    u64 wpair[32];
    {
        const ulonglong2* hrow =
            reinterpret_cast<const ulonglong2*>(Whh + tid * HH);
        #pragma unroll
        for (int q = 0; q < 16; ++q) {
            ulonglong2 t = hrow[q];
            wpair[2 * q] = t.x; wpair[2 * q + 1] = t.y;
        }
    }
    __syncthreads();   // chunk fully dead -> gates/h_s overlay safe

    // =========== forward recurrence: 10 steps ===========
    float cst = 0.0f, hout = 0.0f;

    #pragma unroll 1
    for (int k = 0; k < KK; ++k) {
        // col phase: thread computes gate col c = tid for all 4 nodes
        float gv[BF];
        #pragma unroll
        for (int b = 0; b < BF; ++b) {
            float g = xg[(b * KK + k) * GG + tid];
            if (k > 0) {
                u64 s2 = 0ull;
                const ulonglong2* h2 =
                    reinterpret_cast<const ulonglong2*>(&h_s[b * HH]);
                #pragma unroll
                for (int q = 0; q < 16; ++q) {
                    ulonglong2 hv = h2[q];             // warp-broadcast
                    fma2(s2, hv.x, wpair[2 * q]);
                    fma2(s2, hv.y, wpair[2 * q + 1]);
                }
                float lo, hi; unpack2(s2, lo, hi);
                g += lo + hi;
            }
            gv[b] = g;
        }
        #pragma unroll
        for (int b = 0; b < BF; ++b) gates[b * GG + tid] = gv[b];
        __syncthreads();

        // cell phase: thread owns cell (cb, cj)
        {
            float gi = gates[cb * GG +       cj];
            float gf = gates[cb * GG +  64 + cj];
            float gg = gates[cb * GG + 128 + cj];
            float go = gates[cb * GG + 192 + cj];
            float iv = sigf(gi), fv = sigf(gf);
            float gvv = tanh_fast(gg), ov = sigf(go);
            cst  = (k == 0) ? iv * gvv : fmaf(fv, cst, iv * gvv);
            hout = ov * tanh_fast(cst);
            h_s[cb * HH + cj] = hout;
        }
        __syncthreads();
    }

    // ---- write h_f into out[:, 0:64] ----
    out[(n0 + cb) * (2 * HH) + cj] = hout;
}

// ============================================================================
// Launch
// ============================================================================
extern "C" void kernel_launch(void* const* d_in, const int* in_sizes, int n_in,
                              void* d_out, int out_size)
{
    const int*   nidx  = (const int*)  d_in[0];
    const float* embed = (const float*)d_in[1];
    const float* Wih_f = (const float*)d_in[2];
    const float* Whh_f = (const float*)d_in[3];
    const float* bih_f = (const float*)d_in[4];
    const float* bhh_f = (const float*)d_in[5];
    const float* Wih_b = (const float*)d_in[6];
    // d_in[7] = Whh_b: provably unused (single backward step from h0 = 0)
    const float* bih_b = (const float*)d_in[8];
    const float* bhh_b = (const float*)d_in[9];
    float* out = (float*)d_out;

    const size_t smem = SM_FLOATS * sizeof(float);  // 94464 B -> 2 CTAs/SM
    cudaFuncSetAttribute(lstm_kernel,
                         cudaFuncAttributeMaxDynamicSharedMemorySize, (int)smem);

    lstm_kernel<<<NN / BF, NT, smem>>>(nidx, embed,
                                       Wih_f, Whh_f, bih_f, bhh_f,
                                       Wih_b, bih_b, bhh_b, out);
}